// round 1
// baseline (speedup 1.0000x reference)
#include <cuda_runtime.h>
#include <cstdint>

#define NN  50000
#define NE  800000
#define NET 850000   // NE + NN self loops

// ---------------- scratch (static device globals; no allocs allowed) ----------
__device__ float g_h1[(size_t)NN * 256];   // x @ W1
__device__ float g_f1[(size_t)NN * 256];   // after layer1 (bias+BN+ReLU)
__device__ float g_h2[(size_t)NN * 512];   // f1 @ W2
__device__ float g_es1[NN * 2], g_ed1[NN * 2];
__device__ float g_es2[NN * 2], g_ed2[NN * 2];
__device__ int   g_deg[NN];
__device__ int   g_off[NN + 1];
__device__ int   g_cur[NN];
__device__ int   g_csr[NET];               // src per CSR slot (grouped by dst)

// ---------------- f32x2 packed-FMA helpers (Blackwell FFMA2) ------------------
__device__ __forceinline__ unsigned long long pk2(float x, float y) {
    unsigned long long r;
    asm("mov.b64 %0, {%1, %2};" : "=l"(r)
        : "r"(__float_as_uint(x)), "r"(__float_as_uint(y)));
    return r;
}
__device__ __forceinline__ void fma2(unsigned long long& d, unsigned long long a,
                                     unsigned long long b) {
    asm("fma.rn.f32x2 %0, %1, %2, %3;" : "=l"(d) : "l"(a), "l"(b), "l"(d));
}
__device__ __forceinline__ float2 upk2(unsigned long long v) {
    unsigned int lo, hi;
    asm("mov.b64 {%0, %1}, %2;" : "=r"(lo), "=r"(hi) : "l"(v));
    return make_float2(__uint_as_float(lo), __uint_as_float(hi));
}

// ---------------- CSR build ---------------------------------------------------
__global__ void k_zero_deg() {
    int i = blockIdx.x * blockDim.x + threadIdx.x;
    if (i < NN) g_deg[i] = 0;
}

__global__ void k_hist(const int* __restrict__ dst) {
    int i = blockIdx.x * blockDim.x + threadIdx.x;
    if (i >= NET) return;
    int d = (i < NE) ? dst[i] : (i - NE);
    atomicAdd(&g_deg[d], 1);
}

// single-block exclusive scan over 50000 degrees; also primes the cursor array
__global__ void k_scan() {
    __shared__ int sums[1024];
    const int t  = threadIdx.x;
    const int CH = (NN + 1023) / 1024;      // 49
    int b = t * CH, e = b + CH; if (e > NN) e = NN; if (b > NN) b = NN;
    int s = 0;
    for (int i = b; i < e; i++) s += g_deg[i];
    sums[t] = s;
    __syncthreads();
    for (int off = 1; off < 1024; off <<= 1) {
        int v = (t >= off) ? sums[t - off] : 0;
        __syncthreads();
        sums[t] += v;
        __syncthreads();
    }
    int pre = (t == 0) ? 0 : sums[t - 1];
    for (int i = b; i < e; i++) {
        g_off[i] = pre;
        g_cur[i] = pre;
        pre += g_deg[i];
    }
    if (t == 1023) g_off[NN] = NET;
}

__global__ void k_fill(const int* __restrict__ src, const int* __restrict__ dst) {
    int i = blockIdx.x * blockDim.x + threadIdx.x;
    if (i >= NET) return;
    int s, d;
    if (i < NE) { s = src[i]; d = dst[i]; }
    else        { s = d = i - NE; }
    int pos = atomicAdd(&g_cur[d], 1);
    g_csr[pos] = s;
}

// ---------------- GEMM: C[M,Nn] = A[M,K] @ B[K,Nn], fp32, FFMA2 inner --------
// 128x128 tile, BK=8, 256 threads, 8x8 micro-tile per thread.
__global__ __launch_bounds__(256)
void k_gemm(const float* __restrict__ A, const float* __restrict__ B,
            float* __restrict__ C, int M, int Nn, int K) {
    __shared__ float As[8][132];
    __shared__ float Bs[8][132];

    const int tid = threadIdx.x;
    const int bm  = blockIdx.y * 128;
    const int bn  = blockIdx.x * 128;

    // A loader: 128 rows x 8 k, 2 threads/row (float4 each)
    const int arow = tid >> 1;
    const int acol = (tid & 1) * 4;
    int arowg = bm + arow; if (arowg > M - 1) arowg = M - 1;   // clamp (guarded store)
    const float* Aptr = A + (size_t)arowg * K + acol;

    // B loader: 8 rows x 128 cols, 32 threads/row (float4 each)
    const int brow = tid >> 5;
    const int bcol = (tid & 31) * 4;
    const float* Bptr = B + (size_t)brow * Nn + bn + bcol;

    const int ty = tid >> 4;   // 0..15 -> row group
    const int tx = tid & 15;   // 0..15 -> col group

    unsigned long long acc[8][4];
#pragma unroll
    for (int i = 0; i < 8; i++)
#pragma unroll
        for (int j = 0; j < 4; j++) acc[i][j] = 0ull;   // (0.f,0.f)

    for (int k0 = 0; k0 < K; k0 += 8) {
        float4 av = *(const float4*)Aptr;  Aptr += 8;
        float4 bv = *(const float4*)Bptr;  Bptr += (size_t)8 * Nn;
        As[acol + 0][arow] = av.x;
        As[acol + 1][arow] = av.y;
        As[acol + 2][arow] = av.z;
        As[acol + 3][arow] = av.w;
        *(float4*)&Bs[brow][bcol] = bv;
        __syncthreads();

#pragma unroll
        for (int k = 0; k < 8; k++) {
            float4 a0 = *(float4*)&As[k][ty * 8];
            float4 a1 = *(float4*)&As[k][ty * 8 + 4];
            float4 b0 = *(float4*)&Bs[k][tx * 8];
            float4 b1 = *(float4*)&Bs[k][tx * 8 + 4];
            unsigned long long pb[4];
            pb[0] = pk2(b0.x, b0.y); pb[1] = pk2(b0.z, b0.w);
            pb[2] = pk2(b1.x, b1.y); pb[3] = pk2(b1.z, b1.w);
            float aa[8] = {a0.x, a0.y, a0.z, a0.w, a1.x, a1.y, a1.z, a1.w};
#pragma unroll
            for (int i = 0; i < 8; i++) {
                unsigned long long pa = pk2(aa[i], aa[i]);
#pragma unroll
                for (int j = 0; j < 4; j++) fma2(acc[i][j], pa, pb[j]);
            }
        }
        __syncthreads();
    }

#pragma unroll
    for (int i = 0; i < 8; i++) {
        int r = bm + ty * 8 + i;
        if (r < M) {
            float2 c0 = upk2(acc[i][0]);
            float2 c1 = upk2(acc[i][1]);
            float2 c2 = upk2(acc[i][2]);
            float2 c3 = upk2(acc[i][3]);
            float* o = C + (size_t)r * Nn + bn + tx * 8;
            *(float4*)(o)     = make_float4(c0.x, c0.y, c1.x, c1.y);
            *(float4*)(o + 4) = make_float4(c2.x, c2.y, c3.x, c3.y);
        }
    }
}

// ---------------- per-(node,head) attention coefficients e_src/e_dst ---------
template <int C>
__global__ void k_edot(const float* __restrict__ h, const float* __restrict__ as_,
                       const float* __restrict__ ad_, float* __restrict__ es,
                       float* __restrict__ ed) {
    int gt = blockIdx.x * blockDim.x + threadIdx.x;
    int w = gt >> 5, lane = gt & 31;
    if (w >= NN * 2) return;
    int node = w >> 1, head = w & 1;
    const float* hr = h + (size_t)node * (2 * C) + head * C;
    const float* ar = as_ + head * C;
    const float* dr = ad_ + head * C;
    float s1 = 0.f, s2 = 0.f;
#pragma unroll
    for (int c = lane * 4; c < C; c += 128) {
        float4 hv = *(const float4*)(hr + c);
        float4 av = *(const float4*)(ar + c);
        float4 dv = *(const float4*)(dr + c);
        s1 += hv.x * av.x + hv.y * av.y + hv.z * av.z + hv.w * av.w;
        s2 += hv.x * dv.x + hv.y * dv.y + hv.z * dv.z + hv.w * dv.w;
    }
#pragma unroll
    for (int o = 16; o; o >>= 1) {
        s1 += __shfl_xor_sync(0xffffffffu, s1, o);
        s2 += __shfl_xor_sync(0xffffffffu, s2, o);
    }
    if (lane == 0) { es[w] = s1; ed[w] = s2; }
}

// ---------------- fused attention aggregate + bias + BN(eval) + ReLU ---------
// one warp per (node, head); two passes over that node's in-edges (CSR).
template <int C>
__global__ void k_att(const float* __restrict__ h, const float* __restrict__ es,
                      const float* __restrict__ ed, const float* __restrict__ bb,
                      const float* __restrict__ gg, const float* __restrict__ be,
                      const float* __restrict__ rm, const float* __restrict__ rv,
                      float* __restrict__ outp) {
    int gt = blockIdx.x * blockDim.x + threadIdx.x;
    int w = gt >> 5, lane = gt & 31;
    if (w >= NN * 2) return;
    int node = w >> 1, head = w & 1;
    int beg = g_off[node], end = g_off[node + 1];
    float edv = ed[node * 2 + head];

    // pass A: max over edges
    float m = -1e30f;
    for (int j = beg + lane; j < end; j += 32) {
        int s = g_csr[j];
        float e = es[s * 2 + head] + edv;
        e = e > 0.f ? e : 0.2f * e;
        m = fmaxf(m, e);
    }
#pragma unroll
    for (int o = 16; o; o >>= 1) m = fmaxf(m, __shfl_xor_sync(0xffffffffu, m, o));

    // pass B: weighted feature accumulation
    float4 acc0 = make_float4(0.f, 0.f, 0.f, 0.f);
    float4 acc1 = make_float4(0.f, 0.f, 0.f, 0.f);
    float wsum = 0.f;
    for (int j0 = beg; j0 < end; j0 += 32) {
        int jj = j0 + lane;
        bool val = jj < end;
        int sl = val ? g_csr[jj] : 0;
        float wl = 0.f;
        if (val) {
            float e = es[sl * 2 + head] + edv;
            e = e > 0.f ? e : 0.2f * e;
            wl = __expf(e - m);
        }
        wsum += wl;
        int cnt = end - j0; if (cnt > 32) cnt = 32;
        for (int t = 0; t < cnt; t++) {
            float wv = __shfl_sync(0xffffffffu, wl, t);
            int   sv = __shfl_sync(0xffffffffu, sl, t);
            const float4* p = (const float4*)(h + (size_t)sv * (2 * C) + head * C) + lane;
            float4 v = __ldg(p);
            acc0.x += wv * v.x; acc0.y += wv * v.y;
            acc0.z += wv * v.z; acc0.w += wv * v.w;
            if (C == 256) {
                float4 v2 = __ldg(p + 32);
                acc1.x += wv * v2.x; acc1.y += wv * v2.y;
                acc1.z += wv * v2.z; acc1.w += wv * v2.w;
            }
        }
    }
#pragma unroll
    for (int o = 16; o; o >>= 1) wsum += __shfl_xor_sync(0xffffffffu, wsum, o);
    float inv = 1.0f / (wsum + 1e-16f);

    // epilogue: alpha-normalize, +bias, BN eval, ReLU
    int f0 = head * C + lane * 4;
    {
        float vals[4] = {acc0.x, acc0.y, acc0.z, acc0.w};
        float4 o4;
        float* ov = (float*)&o4;
#pragma unroll
        for (int k = 0; k < 4; k++) {
            int f = f0 + k;
            float o = vals[k] * inv + bb[f];
            o = (o - rm[f]) * rsqrtf(rv[f] + 1e-5f) * gg[f] + be[f];
            ov[k] = fmaxf(o, 0.f);
        }
        *(float4*)(outp + (size_t)node * (2 * C) + f0) = o4;
    }
    if (C == 256) {
        int f1 = f0 + 128;
        float vals[4] = {acc1.x, acc1.y, acc1.z, acc1.w};
        float4 o4;
        float* ov = (float*)&o4;
#pragma unroll
        for (int k = 0; k < 4; k++) {
            int f = f1 + k;
            float o = vals[k] * inv + bb[f];
            o = (o - rm[f]) * rsqrtf(rv[f] + 1e-5f) * gg[f] + be[f];
            ov[k] = fmaxf(o, 0.f);
        }
        *(float4*)(outp + (size_t)node * (2 * C) + f1) = o4;
    }
}

// ---------------- launch -----------------------------------------------------
extern "C" void kernel_launch(void* const* d_in, const int* in_sizes, int n_in,
                              void* d_out, int out_size) {
    const float* x   = (const float*)d_in[0];
    const int*   ei  = (const int*)d_in[1];
    const float* W1  = (const float*)d_in[2];
    const float* as1 = (const float*)d_in[3];
    const float* ad1 = (const float*)d_in[4];
    const float* b1  = (const float*)d_in[5];
    const float* g1  = (const float*)d_in[6];
    const float* be1 = (const float*)d_in[7];
    const float* m1  = (const float*)d_in[8];
    const float* v1  = (const float*)d_in[9];
    const float* W2  = (const float*)d_in[10];
    const float* as2 = (const float*)d_in[11];
    const float* ad2 = (const float*)d_in[12];
    const float* b2  = (const float*)d_in[13];
    const float* g2  = (const float*)d_in[14];
    const float* be2 = (const float*)d_in[15];
    const float* m2  = (const float*)d_in[16];
    const float* v2  = (const float*)d_in[17];
    float* out = (float*)d_out;

    const int* srcp = ei;
    const int* dstp = ei + NE;

    float* h1 = nullptr; float* f1 = nullptr; float* h2 = nullptr;
    cudaGetSymbolAddress((void**)&h1, g_h1);
    cudaGetSymbolAddress((void**)&f1, g_f1);
    cudaGetSymbolAddress((void**)&h2, g_h2);
    float *es1, *ed1, *es2, *ed2;
    cudaGetSymbolAddress((void**)&es1, g_es1);
    cudaGetSymbolAddress((void**)&ed1, g_ed1);
    cudaGetSymbolAddress((void**)&es2, g_es2);
    cudaGetSymbolAddress((void**)&ed2, g_ed2);

    // CSR build (recomputed every launch; deterministic up to fp sum order)
    k_zero_deg<<<(NN + 255) / 256, 256>>>();
    k_hist<<<(NET + 255) / 256, 256>>>(dstp);
    k_scan<<<1, 1024>>>();
    k_fill<<<(NET + 255) / 256, 256>>>(srcp, dstp);

    const int warpBlocks = (NN * 2 * 32) / 256;   // 12500

    // layer 1
    k_gemm<<<dim3(256 / 128, (NN + 127) / 128), 256>>>(x, W1, h1, NN, 256, 128);
    k_edot<128><<<warpBlocks, 256>>>(h1, as1, ad1, es1, ed1);
    k_att<128><<<warpBlocks, 256>>>(h1, es1, ed1, b1, g1, be1, m1, v1, f1);

    // layer 2
    k_gemm<<<dim3(512 / 128, (NN + 127) / 128), 256>>>(f1, W2, h2, NN, 512, 256);
    k_edot<256><<<warpBlocks, 256>>>(h2, as2, ad2, es2, ed2);
    k_att<256><<<warpBlocks, 256>>>(h2, es2, ed2, b2, g2, be2, m2, v2, out);
}

// round 3
// speedup vs baseline: 1.3411x; 1.3411x over previous
#include <cuda_runtime.h>
#include <cuda_bf16.h>
#include <cstdint>

#define NN  50000
#define NE  800000
#define NET 850000   // NE + NN self loops

typedef __nv_bfloat16 bf16;

// ---------------- scratch (static device globals; no allocs allowed) ----------
__device__ float g_h1[(size_t)NN * 256];   // x @ W1 (f32, for attention gather)
__device__ float g_h2[(size_t)NN * 512];   // f1 @ W2 (f32, for attention gather)
__device__ bf16  g_xhi[(size_t)NN * 128], g_xlo[(size_t)NN * 128];
__device__ bf16  g_f1hi[(size_t)NN * 256], g_f1lo[(size_t)NN * 256];
__device__ bf16  g_w1hi[256 * 128], g_w1lo[256 * 128];     // W1^T [N=256,K=128]
__device__ bf16  g_w2hi[512 * 256], g_w2lo[512 * 256];     // W2^T [N=512,K=256]
__device__ float g_es1[NN * 2], g_ed1[NN * 2];
__device__ float g_es2[NN * 2], g_ed2[NN * 2];
__device__ int   g_deg[NN];
__device__ int   g_off[NN + 1];
__device__ int   g_cur[NN];
__device__ int   g_csr[NET];               // src per CSR slot (grouped by dst)

// ---------------- PTX helpers (arch-generic: ldmatrix + mma.sync) -------------
__device__ __forceinline__ uint32_t s2u(const void* p) {
    uint32_t a;
    asm("{ .reg .u64 t; cvta.to.shared.u64 t, %1; cvt.u32.u64 %0, t; }"
        : "=r"(a) : "l"(p));
    return a;
}

__device__ __forceinline__ void ldsm4(uint32_t* r, uint32_t addr) {
    asm volatile("ldmatrix.sync.aligned.m8n8.x4.shared.b16 {%0,%1,%2,%3}, [%4];"
                 : "=r"(r[0]), "=r"(r[1]), "=r"(r[2]), "=r"(r[3]) : "r"(addr));
}

__device__ __forceinline__ void mma16816(float* d, const uint32_t* a,
                                         uint32_t b0, uint32_t b1) {
    asm volatile(
        "mma.sync.aligned.m16n8k16.row.col.f32.bf16.bf16.f32 "
        "{%0,%1,%2,%3}, {%4,%5,%6,%7}, {%8,%9}, {%0,%1,%2,%3};"
        : "+f"(d[0]), "+f"(d[1]), "+f"(d[2]), "+f"(d[3])
        : "r"(a[0]), "r"(a[1]), "r"(a[2]), "r"(a[3]), "r"(b0), "r"(b1));
}

// ---------------- fp32 -> bf16 hi/lo split ------------------------------------
__global__ void k_split(const float* __restrict__ in, bf16* __restrict__ hi,
                        bf16* __restrict__ lo, int n) {
    int i = blockIdx.x * blockDim.x + threadIdx.x;
    if (i >= n) return;
    float v = in[i];
    bf16 h = __float2bfloat16(v);
    hi[i] = h;
    lo[i] = __float2bfloat16(v - __bfloat162float(h));
}

// W[K,N] row-major -> Wt[N,K] hi/lo split
__global__ void k_splitT(const float* __restrict__ W, bf16* __restrict__ hiT,
                         bf16* __restrict__ loT, int K, int N) {
    int i = blockIdx.x * blockDim.x + threadIdx.x;
    if (i >= K * N) return;
    int k = i / N, n = i % N;
    float v = W[i];
    bf16 h = __float2bfloat16(v);
    hiT[(size_t)n * K + k] = h;
    loT[(size_t)n * K + k] = __float2bfloat16(v - __bfloat162float(h));
}

// ---------------- CSR build ---------------------------------------------------
__global__ void k_zero_deg() {
    int i = blockIdx.x * blockDim.x + threadIdx.x;
    if (i < NN) g_deg[i] = 0;
}

__global__ void k_hist(const int* __restrict__ dst) {
    int i = blockIdx.x * blockDim.x + threadIdx.x;
    if (i >= NET) return;
    int d = (i < NE) ? dst[i] : (i - NE);
    atomicAdd(&g_deg[d], 1);
}

__global__ void k_scan() {
    __shared__ int sums[1024];
    const int t  = threadIdx.x;
    const int CH = (NN + 1023) / 1024;
    int b = t * CH, e = b + CH; if (e > NN) e = NN; if (b > NN) b = NN;
    int s = 0;
    for (int i = b; i < e; i++) s += g_deg[i];
    sums[t] = s;
    __syncthreads();
    for (int off = 1; off < 1024; off <<= 1) {
        int v = (t >= off) ? sums[t - off] : 0;
        __syncthreads();
        sums[t] += v;
        __syncthreads();
    }
    int pre = (t == 0) ? 0 : sums[t - 1];
    for (int i = b; i < e; i++) {
        g_off[i] = pre;
        g_cur[i] = pre;
        pre += g_deg[i];
    }
    if (t == 1023) g_off[NN] = NET;
}

__global__ void k_fill(const int* __restrict__ src, const int* __restrict__ dst) {
    int i = blockIdx.x * blockDim.x + threadIdx.x;
    if (i >= NET) return;
    int s, d;
    if (i < NE) { s = src[i]; d = dst[i]; }
    else        { s = d = i - NE; }
    int pos = atomicAdd(&g_cur[d], 1);
    g_csr[pos] = s;
}

// ---------------- HMMA GEMM: C[M,Nn] = A[M,K] @ Wt[Nn,K]^T --------------------
// bf16 split: C = Ahi*Bhi + Ahi*Blo + Alo*Bhi  (fp32 accumulators)
// 128x128 tile / CTA, 8 warps (2x4), warp tile 64x32, BK=32, reg prefetch.
#define RS 40   // smem row stride in bf16 elements (80B, ldmatrix conflict-free)

__global__ __launch_bounds__(256)
void k_mma(const bf16* __restrict__ Ahi, const bf16* __restrict__ Alo,
           const bf16* __restrict__ Bhi, const bf16* __restrict__ Blo,
           float* __restrict__ C, int M, int Nn, int K) {
    __shared__ __align__(16) bf16 sAh[128 * RS];
    __shared__ __align__(16) bf16 sAl[128 * RS];
    __shared__ __align__(16) bf16 sBh[128 * RS];
    __shared__ __align__(16) bf16 sBl[128 * RS];

    const int tid = threadIdx.x, lane = tid & 31, wid = tid >> 5;
    const int bm = blockIdx.y * 128, bn = blockIdx.x * 128;
    const int wm = (wid & 1) * 64;        // warp m offset in tile
    const int wn = (wid >> 1) * 32;       // warp n offset in tile

    // gmem load coords (2 uint4 rounds per tile per thread)
    int lrow[2], lc4[2];
    size_t aoffs[2], boffs[2];
#pragma unroll
    for (int j = 0; j < 2; j++) {
        int idx = tid + j * 256;
        lrow[j] = idx >> 2;
        lc4[j]  = idx & 3;
        int ra = bm + lrow[j]; if (ra >= M) ra = M - 1;
        aoffs[j] = (size_t)ra * K + lc4[j] * 8;
        boffs[j] = (size_t)(bn + lrow[j]) * K + lc4[j] * 8;
    }

    // ldmatrix per-lane base byte offsets
    const int li = lane >> 3, l8 = lane & 7;
    const uint32_t aA = (uint32_t)(((wm + (li & 1) * 8 + l8) * RS + (li >> 1) * 8) * 2);
    const uint32_t aB = (uint32_t)(((wn + (li >> 1) * 8 + l8) * RS + (li & 1) * 8) * 2);
    const uint32_t bAh = s2u(sAh) + aA, bAl = s2u(sAl) + aA;
    const uint32_t bBh = s2u(sBh) + aB, bBl = s2u(sBl) + aB;

    float acc[4][4][4];
#pragma unroll
    for (int i = 0; i < 4; i++)
#pragma unroll
        for (int j = 0; j < 4; j++)
#pragma unroll
            for (int k = 0; k < 4; k++) acc[i][j][k] = 0.f;

    uint4 pf[8];
    const int nch = K >> 5;

    // prefetch chunk 0
#pragma unroll
    for (int j = 0; j < 2; j++) {
        pf[j]     = *(const uint4*)(Ahi + aoffs[j]);
        pf[2 + j] = *(const uint4*)(Alo + aoffs[j]);
        pf[4 + j] = *(const uint4*)(Bhi + boffs[j]);
        pf[6 + j] = *(const uint4*)(Blo + boffs[j]);
    }

    for (int c = 0; c < nch; c++) {
        // store prefetched chunk to smem
#pragma unroll
        for (int j = 0; j < 2; j++) {
            uint32_t so = (uint32_t)(lrow[j] * RS + lc4[j] * 8);
            *(uint4*)(sAh + so) = pf[j];
            *(uint4*)(sAl + so) = pf[2 + j];
            *(uint4*)(sBh + so) = pf[4 + j];
            *(uint4*)(sBl + so) = pf[6 + j];
        }
        __syncthreads();

        // prefetch next chunk
        if (c + 1 < nch) {
            size_t kadv = (size_t)(c + 1) * 32;
#pragma unroll
            for (int j = 0; j < 2; j++) {
                pf[j]     = *(const uint4*)(Ahi + aoffs[j] + kadv);
                pf[2 + j] = *(const uint4*)(Alo + aoffs[j] + kadv);
                pf[4 + j] = *(const uint4*)(Bhi + boffs[j] + kadv);
                pf[6 + j] = *(const uint4*)(Blo + boffs[j] + kadv);
            }
        }

        // MMA over this chunk (two k16 steps)
#pragma unroll
        for (int ks = 0; ks < 2; ks++) {
            const uint32_t kb = (uint32_t)(ks * 16 * 2);
            uint32_t ah[4][4], al[4][4], bh[2][4], bl[2][4];
#pragma unroll
            for (int mt = 0; mt < 4; mt++) {
                uint32_t off = (uint32_t)(mt * 16 * RS * 2) + kb;
                ldsm4(ah[mt], bAh + off);
                ldsm4(al[mt], bAl + off);
            }
#pragma unroll
            for (int p = 0; p < 2; p++) {
                uint32_t off = (uint32_t)(p * 16 * RS * 2) + kb;
                ldsm4(bh[p], bBh + off);
                ldsm4(bl[p], bBl + off);
            }
#pragma unroll
            for (int mt = 0; mt < 4; mt++)
#pragma unroll
                for (int nt = 0; nt < 4; nt++) {
                    const int p = nt >> 1, o = (nt & 1) * 2;
                    mma16816(acc[mt][nt], ah[mt], bh[p][o], bh[p][o + 1]);
                    mma16816(acc[mt][nt], ah[mt], bl[p][o], bl[p][o + 1]);
                    mma16816(acc[mt][nt], al[mt], bh[p][o], bh[p][o + 1]);
                }
        }
        __syncthreads();
    }

    // epilogue: c-fragment m16n8 -> lane l: (row l/4 [+8], col 2*(l%4) [+1])
#pragma unroll
    for (int mt = 0; mt < 4; mt++) {
        int r0 = bm + wm + mt * 16 + (lane >> 2);
#pragma unroll
        for (int nt = 0; nt < 4; nt++) {
            int col = bn + wn + nt * 8 + (lane & 3) * 2;
            if (r0 < M)
                *(float2*)(C + (size_t)r0 * Nn + col) =
                    make_float2(acc[mt][nt][0], acc[mt][nt][1]);
            if (r0 + 8 < M)
                *(float2*)(C + (size_t)(r0 + 8) * Nn + col) =
                    make_float2(acc[mt][nt][2], acc[mt][nt][3]);
        }
    }
}

// ---------------- per-(node,head) attention coefficients e_src/e_dst ---------
template <int C>
__global__ void k_edot(const float* __restrict__ h, const float* __restrict__ as_,
                       const float* __restrict__ ad_, float* __restrict__ es,
                       float* __restrict__ ed) {
    int gt = blockIdx.x * blockDim.x + threadIdx.x;
    int w = gt >> 5, lane = gt & 31;
    if (w >= NN * 2) return;
    int node = w >> 1, head = w & 1;
    const float* hr = h + (size_t)node * (2 * C) + head * C;
    const float* ar = as_ + head * C;
    const float* dr = ad_ + head * C;
    float s1 = 0.f, s2 = 0.f;
#pragma unroll
    for (int c = lane * 4; c < C; c += 128) {
        float4 hv = *(const float4*)(hr + c);
        float4 av = *(const float4*)(ar + c);
        float4 dv = *(const float4*)(dr + c);
        s1 += hv.x * av.x + hv.y * av.y + hv.z * av.z + hv.w * av.w;
        s2 += hv.x * dv.x + hv.y * dv.y + hv.z * dv.z + hv.w * dv.w;
    }
#pragma unroll
    for (int o = 16; o; o >>= 1) {
        s1 += __shfl_xor_sync(0xffffffffu, s1, o);
        s2 += __shfl_xor_sync(0xffffffffu, s2, o);
    }
    if (lane == 0) { es[w] = s1; ed[w] = s2; }
}

// ---------------- fused attention aggregate + bias + BN(eval) + ReLU ---------
// one warp per (node, head); two passes over that node's in-edges (CSR).
// C==128: writes bf16 hi/lo (feeds next GEMM).  C==256: writes f32 to out.
template <int C>
__global__ void k_att(const float* __restrict__ h, const float* __restrict__ es,
                      const float* __restrict__ ed, const float* __restrict__ bb,
                      const float* __restrict__ gg, const float* __restrict__ be,
                      const float* __restrict__ rm, const float* __restrict__ rv,
                      float* __restrict__ outp, bf16* __restrict__ ohi,
                      bf16* __restrict__ olo) {
    int gt = blockIdx.x * blockDim.x + threadIdx.x;
    int w = gt >> 5, lane = gt & 31;
    if (w >= NN * 2) return;
    int node = w >> 1, head = w & 1;
    int beg = g_off[node], end = g_off[node + 1];
    float edv = ed[node * 2 + head];

    // pass A: max over edges
    float m = -1e30f;
    for (int j = beg + lane; j < end; j += 32) {
        int s = g_csr[j];
        float e = es[s * 2 + head] + edv;
        e = e > 0.f ? e : 0.2f * e;
        m = fmaxf(m, e);
    }
#pragma unroll
    for (int o = 16; o; o >>= 1) m = fmaxf(m, __shfl_xor_sync(0xffffffffu, m, o));

    // pass B: weighted feature accumulation
    float4 acc0 = make_float4(0.f, 0.f, 0.f, 0.f);
    float4 acc1 = make_float4(0.f, 0.f, 0.f, 0.f);
    float wsum = 0.f;
    for (int j0 = beg; j0 < end; j0 += 32) {
        int jj = j0 + lane;
        bool val = jj < end;
        int sl = val ? g_csr[jj] : 0;
        float wl = 0.f;
        if (val) {
            float e = es[sl * 2 + head] + edv;
            e = e > 0.f ? e : 0.2f * e;
            wl = __expf(e - m);
        }
        wsum += wl;
        int cnt = end - j0; if (cnt > 32) cnt = 32;
        for (int t = 0; t < cnt; t++) {
            float wv = __shfl_sync(0xffffffffu, wl, t);
            int   sv = __shfl_sync(0xffffffffu, sl, t);
            const float4* p = (const float4*)(h + (size_t)sv * (2 * C) + head * C) + lane;
            float4 v = __ldg(p);
            acc0.x += wv * v.x; acc0.y += wv * v.y;
            acc0.z += wv * v.z; acc0.w += wv * v.w;
            if (C == 256) {
                float4 v2 = __ldg(p + 32);
                acc1.x += wv * v2.x; acc1.y += wv * v2.y;
                acc1.z += wv * v2.z; acc1.w += wv * v2.w;
            }
        }
    }
#pragma unroll
    for (int o = 16; o; o >>= 1) wsum += __shfl_xor_sync(0xffffffffu, wsum, o);
    float inv = 1.0f / (wsum + 1e-16f);

    // epilogue: alpha-normalize, +bias, BN eval, ReLU
    int f0 = head * C + lane * 4;
    float res0[4];
    {
        float vals[4] = {acc0.x, acc0.y, acc0.z, acc0.w};
#pragma unroll
        for (int k = 0; k < 4; k++) {
            int f = f0 + k;
            float o = vals[k] * inv + bb[f];
            o = (o - rm[f]) * rsqrtf(rv[f] + 1e-5f) * gg[f] + be[f];
            res0[k] = fmaxf(o, 0.f);
        }
    }
    if (C == 128) {
        // bf16 hi/lo split output for the next GEMM
        size_t idx = (size_t)node * (2 * C) + f0;
        bf16 h0 = __float2bfloat16(res0[0]);
        bf16 h1 = __float2bfloat16(res0[1]);
        bf16 h2 = __float2bfloat16(res0[2]);
        bf16 h3 = __float2bfloat16(res0[3]);
        __nv_bfloat162* ph = (__nv_bfloat162*)(ohi + idx);
        ph[0] = __nv_bfloat162(h0, h1);
        ph[1] = __nv_bfloat162(h2, h3);
        __nv_bfloat162* pl = (__nv_bfloat162*)(olo + idx);
        pl[0] = __nv_bfloat162(__float2bfloat16(res0[0] - __bfloat162float(h0)),
                               __float2bfloat16(res0[1] - __bfloat162float(h1)));
        pl[1] = __nv_bfloat162(__float2bfloat16(res0[2] - __bfloat162float(h2)),
                               __float2bfloat16(res0[3] - __bfloat162float(h3)));
    } else {
        *(float4*)(outp + (size_t)node * (2 * C) + f0) =
            make_float4(res0[0], res0[1], res0[2], res0[3]);
        int f1 = f0 + 128;
        float vals[4] = {acc1.x, acc1.y, acc1.z, acc1.w};
        float4 o4;
        float* ov = (float*)&o4;
#pragma unroll
        for (int k = 0; k < 4; k++) {
            int f = f1 + k;
            float o = vals[k] * inv + bb[f];
            o = (o - rm[f]) * rsqrtf(rv[f] + 1e-5f) * gg[f] + be[f];
            ov[k] = fmaxf(o, 0.f);
        }
        *(float4*)(outp + (size_t)node * (2 * C) + f1) = o4;
    }
}

// ---------------- launch -----------------------------------------------------
extern "C" void kernel_launch(void* const* d_in, const int* in_sizes, int n_in,
                              void* d_out, int out_size) {
    const float* x   = (const float*)d_in[0];
    const int*   ei  = (const int*)d_in[1];
    const float* W1  = (const float*)d_in[2];
    const float* as1 = (const float*)d_in[3];
    const float* ad1 = (const float*)d_in[4];
    const float* b1  = (const float*)d_in[5];
    const float* g1  = (const float*)d_in[6];
    const float* be1 = (const float*)d_in[7];
    const float* m1  = (const float*)d_in[8];
    const float* v1  = (const float*)d_in[9];
    const float* W2  = (const float*)d_in[10];
    const float* as2 = (const float*)d_in[11];
    const float* ad2 = (const float*)d_in[12];
    const float* b2  = (const float*)d_in[13];
    const float* g2  = (const float*)d_in[14];
    const float* be2 = (const float*)d_in[15];
    const float* m2  = (const float*)d_in[16];
    const float* v2  = (const float*)d_in[17];
    float* out = (float*)d_out;

    const int* srcp = ei;
    const int* dstp = ei + NE;

    float *h1, *h2;
    cudaGetSymbolAddress((void**)&h1, g_h1);
    cudaGetSymbolAddress((void**)&h2, g_h2);
    bf16 *xhi, *xlo, *f1hi, *f1lo, *w1hi, *w1lo, *w2hi, *w2lo;
    cudaGetSymbolAddress((void**)&xhi, g_xhi);
    cudaGetSymbolAddress((void**)&xlo, g_xlo);
    cudaGetSymbolAddress((void**)&f1hi, g_f1hi);
    cudaGetSymbolAddress((void**)&f1lo, g_f1lo);
    cudaGetSymbolAddress((void**)&w1hi, g_w1hi);
    cudaGetSymbolAddress((void**)&w1lo, g_w1lo);
    cudaGetSymbolAddress((void**)&w2hi, g_w2hi);
    cudaGetSymbolAddress((void**)&w2lo, g_w2lo);
    float *es1, *ed1, *es2, *ed2;
    cudaGetSymbolAddress((void**)&es1, g_es1);
    cudaGetSymbolAddress((void**)&ed1, g_ed1);
    cudaGetSymbolAddress((void**)&es2, g_es2);
    cudaGetSymbolAddress((void**)&ed2, g_ed2);

    // input conversions
    k_split<<<(NN * 128 + 255) / 256, 256>>>(x, xhi, xlo, NN * 128);
    k_splitT<<<(128 * 256 + 255) / 256, 256>>>(W1, w1hi, w1lo, 128, 256);
    k_splitT<<<(256 * 512 + 255) / 256, 256>>>(W2, w2hi, w2lo, 256, 512);

    // CSR build
    k_zero_deg<<<(NN + 255) / 256, 256>>>();
    k_hist<<<(NET + 255) / 256, 256>>>(dstp);
    k_scan<<<1, 1024>>>();
    k_fill<<<(NET + 255) / 256, 256>>>(srcp, dstp);

    const int warpBlocks = (NN * 2 * 32) / 256;   // 12500
    const int mTiles = (NN + 127) / 128;          // 391

    // layer 1
    k_mma<<<dim3(256 / 128, mTiles), 256>>>(xhi, xlo, w1hi, w1lo, h1, NN, 256, 128);
    k_edot<128><<<warpBlocks, 256>>>(h1, as1, ad1, es1, ed1);
    k_att<128><<<warpBlocks, 256>>>(h1, es1, ed1, b1, g1, be1, m1, v1, nullptr, f1hi, f1lo);

    // layer 2
    k_mma<<<dim3(512 / 128, mTiles), 256>>>(f1hi, f1lo, w2hi, w2lo, h2, NN, 512, 256);
    k_edot<256><<<warpBlocks, 256>>>(h2, as2, ad2, es2, ed2);
    k_att<256><<<warpBlocks, 256>>>(h2, es2, ed2, b2, g2, be2, m2, v2, out, nullptr, nullptr);
}